// round 9
// baseline (speedup 1.0000x reference)
#include <cuda_runtime.h>
#include <cstdint>

// Problem constants (fixed by dataset).
#define U_C  100000
#define I_C  50000
#define N_C  150000
#define ROWS_TOT (N_C + U_C + I_C)       // 300000
#define CAP  24                          // perm = 57.6MB -> L2-resident
#define OVF_CAP 65536

#define TPB 256
#define D64 64
#define COCAP 592                        // capped grid for co-resident phase (~4 blocks/SM)

__device__ int  d_curs[ROWS_TOT];
__device__ int2 d_perm[(size_t)ROWS_TOT * CAP];
__device__ int  d_ovf_count;
__device__ int4 d_ovf[OVF_CAP];          // {key, col, val_bits, 0}

// ---------------- build: grid-stride scatter over one or two lists ----------
__global__ void __launch_bounds__(TPB) scatter_list(const int* __restrict__ rows,
                                                    const int* __restrict__ cols,
                                                    const float* __restrict__ vals,
                                                    int E, int key_base) {
    for (int e = blockIdx.x * TPB + threadIdx.x; e < E; e += gridDim.x * TPB) {
        int key = key_base + __ldcs(rows + e);
        int c   = __ldcs(cols + e);
        float v = __ldcs(vals + e);
        int pos = atomicAdd(&d_curs[key], 1);
        if (pos < CAP) {
            d_perm[(size_t)key * CAP + pos] = make_int2(c, __float_as_int(v));
        } else {
            int o = atomicAdd(&d_ovf_count, 1);
            if (o < OVF_CAP) d_ovf[o] = make_int4(key, c, __float_as_int(v), 0);
        }
    }
}

// user + item lists fused into one launch.
__global__ void __launch_bounds__(TPB) scatter_ui(const int* __restrict__ ur,
                                                  const int* __restrict__ uc,
                                                  const float* __restrict__ uv,
                                                  const int* __restrict__ ir,
                                                  const int* __restrict__ ic,
                                                  const float* __restrict__ iv,
                                                  int EU, int EI, int N_, int U_) {
    int ET = EU + EI;
    for (int e = blockIdx.x * TPB + threadIdx.x; e < ET; e += gridDim.x * TPB) {
        int key, c; float v;
        if (e < EU) {
            key = N_ + __ldcs(ur + e);           c = __ldcs(uc + e);  v = __ldcs(uv + e);
        } else {
            int k = e - EU;
            key = N_ + U_ + __ldcs(ir + k);      c = __ldcs(ic + k);  v = __ldcs(iv + k);
        }
        int pos = atomicAdd(&d_curs[key], 1);
        if (pos < CAP) {
            d_perm[(size_t)key * CAP + pos] = make_int2(c, __float_as_int(v));
        } else {
            int o = atomicAdd(&d_ovf_count, 1);
            if (o < OVF_CAP) d_ovf[o] = make_int4(key, c, __float_as_int(v), 0);
        }
    }
}

// ---------------- main: grid-stride over key range ---------------
__global__ void __launch_bounds__(TPB) csr_spmm_range(const float* __restrict__ user_emb,
                                                      const float* __restrict__ item_emb,
                                                      float* __restrict__ out,
                                                      int row_base, int n_rows,
                                                      int N_, int U_) {
    long long total = (long long)n_rows * 16;
    for (long long t = (long long)blockIdx.x * TPB + threadIdx.x; t < total;
         t += (long long)gridDim.x * TPB) {
        int rr   = (int)(t >> 4);
        int lane = (int)(t & 15);
        int key  = row_base + rr;

        const float* src0;
        const float* src1;
        int U_split;
        if (key < N_) {                    // graph: concat(user, item) source
            src0 = user_emb; src1 = item_emb; U_split = U_;
        } else if (key < N_ + U_) {        // user SpMM
            src0 = user_emb; src1 = user_emb; U_split = 0x7FFFFFFF;
        } else {                           // item SpMM
            src0 = item_emb; src1 = item_emb; U_split = 0x7FFFFFFF;
        }

        int deg = min(d_curs[key], CAP);
        const int2* bucket = d_perm + (size_t)key * CAP;

        float4 acc = make_float4(0.f, 0.f, 0.f, 0.f);

        int j = 0;
        for (; j + 4 <= deg; j += 4) {
            int2 e0 = __ldcs(bucket + j);
            int2 e1 = __ldcs(bucket + j + 1);
            int2 e2 = __ldcs(bucket + j + 2);
            int2 e3 = __ldcs(bucket + j + 3);
            const float* p0 = (e0.x < U_split) ? src0 + (long long)e0.x * D64 : src1 + (long long)(e0.x - U_split) * D64;
            const float* p1 = (e1.x < U_split) ? src0 + (long long)e1.x * D64 : src1 + (long long)(e1.x - U_split) * D64;
            const float* p2 = (e2.x < U_split) ? src0 + (long long)e2.x * D64 : src1 + (long long)(e2.x - U_split) * D64;
            const float* p3 = (e3.x < U_split) ? src0 + (long long)e3.x * D64 : src1 + (long long)(e3.x - U_split) * D64;
            float4 x0 = reinterpret_cast<const float4*>(p0)[lane];
            float4 x1 = reinterpret_cast<const float4*>(p1)[lane];
            float4 x2 = reinterpret_cast<const float4*>(p2)[lane];
            float4 x3 = reinterpret_cast<const float4*>(p3)[lane];
            float v0 = __int_as_float(e0.y), v1 = __int_as_float(e1.y);
            float v2 = __int_as_float(e2.y), v3 = __int_as_float(e3.y);
            acc.x = fmaf(v0, x0.x, acc.x); acc.y = fmaf(v0, x0.y, acc.y); acc.z = fmaf(v0, x0.z, acc.z); acc.w = fmaf(v0, x0.w, acc.w);
            acc.x = fmaf(v1, x1.x, acc.x); acc.y = fmaf(v1, x1.y, acc.y); acc.z = fmaf(v1, x1.z, acc.z); acc.w = fmaf(v1, x1.w, acc.w);
            acc.x = fmaf(v2, x2.x, acc.x); acc.y = fmaf(v2, x2.y, acc.y); acc.z = fmaf(v2, x2.z, acc.z); acc.w = fmaf(v2, x2.w, acc.w);
            acc.x = fmaf(v3, x3.x, acc.x); acc.y = fmaf(v3, x3.y, acc.y); acc.z = fmaf(v3, x3.z, acc.z); acc.w = fmaf(v3, x3.w, acc.w);
        }
        for (; j < deg; j++) {
            int2 e = __ldcs(bucket + j);
            const float* p = (e.x < U_split) ? src0 + (long long)e.x * D64 : src1 + (long long)(e.x - U_split) * D64;
            float4 x = reinterpret_cast<const float4*>(p)[lane];
            float v = __int_as_float(e.y);
            acc.x = fmaf(v, x.x, acc.x); acc.y = fmaf(v, x.y, acc.y);
            acc.z = fmaf(v, x.z, acc.z); acc.w = fmaf(v, x.w, acc.w);
        }

        __stcs(reinterpret_cast<float4*>(out + (long long)key * D64) + lane, acc);
    }
}

// ---------------- overflow fixup (exactness; small) ----------------
__global__ void __launch_bounds__(TPB) fixup(const float* __restrict__ user_emb,
                                             const float* __restrict__ item_emb,
                                             float* __restrict__ out,
                                             int N_, int U_) {
    int n = min(d_ovf_count, OVF_CAP);
    long long total = (long long)n * 16;
    for (long long t = blockIdx.x * (long long)TPB + threadIdx.x; t < total;
         t += (long long)gridDim.x * TPB) {
        int idx  = (int)(t >> 4);
        int lane = (int)(t & 15);
        int4 e = d_ovf[idx];
        int key = e.x, c = e.y;
        float v = __int_as_float(e.z);
        const float* src;
        if (key < N_)            src = (c < U_) ? user_emb + (long long)c * D64
                                                : item_emb + (long long)(c - U_) * D64;
        else if (key < N_ + U_)  src = user_emb + (long long)c * D64;
        else                     src = item_emb + (long long)c * D64;
        float4 x = reinterpret_cast<const float4*>(src)[lane];
        x.x *= v; x.y *= v; x.z *= v; x.w *= v;
        float4* d = reinterpret_cast<float4*>(out + (long long)key * D64) + lane;
        asm volatile("red.global.add.v4.f32 [%0], {%1,%2,%3,%4};"
                     :: "l"(d), "f"(x.x), "f"(x.y), "f"(x.z), "f"(x.w)
                     : "memory");
    }
}

extern "C" void kernel_launch(void* const* d_in, const int* in_sizes, int n_in,
                              void* d_out, int out_size) {
    const float* user_emb = (const float*)d_in[0];
    const float* item_emb = (const float*)d_in[1];
    const int*   g_rows = (const int*)d_in[2];
    const int*   g_cols = (const int*)d_in[3];
    const float* g_vals = (const float*)d_in[4];
    const int*   u_rows = (const int*)d_in[5];
    const int*   u_cols = (const int*)d_in[6];
    const float* u_vals = (const float*)d_in[7];
    const int*   i_rows = (const int*)d_in[8];
    const int*   i_cols = (const int*)d_in[9];
    const float* i_vals = (const float*)d_in[10];

    float* out = (float*)d_out;

    const int U_ = in_sizes[0] / D64;   // 100000
    const int I_ = in_sizes[1] / D64;   // 50000
    const int N_ = U_ + I_;
    const int EG = in_sizes[2];
    const int EU = in_sizes[5];
    const int EI = in_sizes[8];
    const int ROWS = N_ + U_ + I_;

    // Zero cursors + overflow counter.
    void* curs_ptr = nullptr;
    cudaGetSymbolAddress(&curs_ptr, d_curs);
    cudaMemsetAsync(curs_ptr, 0, (size_t)ROWS * sizeof(int), 0);
    void* ovf_ptr = nullptr;
    cudaGetSymbolAddress(&ovf_ptr, d_ovf_count);
    cudaMemsetAsync(ovf_ptr, 0, sizeof(int), 0);

    cudaStream_t s2;
    cudaStreamCreateWithFlags(&s2, cudaStreamNonBlocking);
    cudaEvent_t evFork, evUI, evJoin;
    cudaEventCreateWithFlags(&evFork, cudaEventDisableTiming);
    cudaEventCreateWithFlags(&evUI,   cudaEventDisableTiming);
    cudaEventCreateWithFlags(&evJoin, cudaEventDisableTiming);

    // Fork s2 after memsets.
    cudaEventRecord(evFork, 0);
    cudaStreamWaitEvent(s2, evFork, 0);

    // Phase 1 (s2): user+item scatter, full machine.
    {
        int ET = EU + EI;
        int blocks = (ET + TPB - 1) / TPB;
        scatter_ui<<<blocks, TPB, 0, s2>>>(u_rows, u_cols, u_vals,
                                           i_rows, i_cols, i_vals,
                                           EU, EI, N_, U_);
        cudaEventRecord(evUI, s2);
    }

    // Phase 2: heterogeneous overlap — mainUI (LTS-BW-bound) on s2 concurrent
    // with scatterG (L1tex-wavefront-bound) on s0. Both grids capped so they
    // co-reside on the SMs.
    {
        int n_rows = U_ + I_;
        csr_spmm_range<<<COCAP, TPB, 0, s2>>>(user_emb, item_emb, out,
                                              N_, n_rows, N_, U_);
        cudaEventRecord(evJoin, s2);
    }
    cudaStreamWaitEvent(0, evUI, 0);   // scatterG only needs memsets; but keep
                                       // it ordered after phase-1 launch window
    scatter_list<<<COCAP, TPB>>>(g_rows, g_cols, g_vals, EG, 0);

    // Phase 3 (s0): graph main, full machine.
    {
        int blocks = (N_ * 16 + TPB - 1) / TPB;
        csr_spmm_range<<<blocks, TPB>>>(user_emb, item_emb, out, 0, N_, N_, U_);
    }

    // Join + exact overflow fixup.
    cudaStreamWaitEvent(0, evJoin, 0);
    fixup<<<64, TPB>>>(user_emb, item_emb, out, N_, U_);

    cudaEventDestroy(evFork);
    cudaEventDestroy(evUI);
    cudaEventDestroy(evJoin);
    cudaStreamDestroy(s2);
}

// round 10
// speedup vs baseline: 1.0081x; 1.0081x over previous
#include <cuda_runtime.h>
#include <cstdint>

// Problem constants (fixed by dataset).
#define U_C  100000
#define I_C  50000
#define N_C  150000
#define ROWS_TOT (N_C + U_C + I_C)       // 300000
#define CAP  24                          // perm = 57.6MB -> L2-resident
#define OVF_CAP 65536

#define TPB 256
#define D64 64

__device__ int  d_curs[ROWS_TOT];
__device__ int2 d_perm[(size_t)ROWS_TOT * CAP];
__device__ int  d_ovf_count;
__device__ int4 d_ovf[OVF_CAP];          // {key, col, val_bits, 0}

// ---------------- build: direct-indexed scatter ----------------
__global__ void __launch_bounds__(TPB) scatter_list(const int* __restrict__ rows,
                                                    const int* __restrict__ cols,
                                                    const float* __restrict__ vals,
                                                    int E, int key_base) {
    int e = blockIdx.x * TPB + threadIdx.x;
    if (e >= E) return;
    int key = key_base + __ldcs(rows + e);
    int c   = __ldcs(cols + e);
    float v = __ldcs(vals + e);
    int pos = atomicAdd(&d_curs[key], 1);
    if (pos < CAP) {
        d_perm[(size_t)key * CAP + pos] = make_int2(c, __float_as_int(v));
    } else {
        int o = atomicAdd(&d_ovf_count, 1);
        if (o < OVF_CAP) d_ovf[o] = make_int4(key, c, __float_as_int(v), 0);
    }
}

// user + item lists fused into one launch (direct index).
__global__ void __launch_bounds__(TPB) scatter_ui(const int* __restrict__ ur,
                                                  const int* __restrict__ uc,
                                                  const float* __restrict__ uv,
                                                  const int* __restrict__ ir,
                                                  const int* __restrict__ ic,
                                                  const float* __restrict__ iv,
                                                  int EU, int EI, int N_, int U_) {
    int e = blockIdx.x * TPB + threadIdx.x;
    if (e >= EU + EI) return;
    int key, c; float v;
    if (e < EU) {
        key = N_ + __ldcs(ur + e);       c = __ldcs(uc + e);  v = __ldcs(uv + e);
    } else {
        int k = e - EU;
        key = N_ + U_ + __ldcs(ir + k);  c = __ldcs(ic + k);  v = __ldcs(iv + k);
    }
    int pos = atomicAdd(&d_curs[key], 1);
    if (pos < CAP) {
        d_perm[(size_t)key * CAP + pos] = make_int2(c, __float_as_int(v));
    } else {
        int o = atomicAdd(&d_ovf_count, 1);
        if (o < OVF_CAP) d_ovf[o] = make_int4(key, c, __float_as_int(v), 0);
    }
}

// ---------------- main: direct-indexed over key range ---------------
// 16 threads per destination row; register accumulation; streaming store.
__global__ void __launch_bounds__(TPB) csr_spmm_range(const float* __restrict__ user_emb,
                                                      const float* __restrict__ item_emb,
                                                      float* __restrict__ out,
                                                      int row_base, int n_rows,
                                                      int N_, int U_) {
    int tid  = blockIdx.x * TPB + threadIdx.x;
    int rr   = tid >> 4;
    int lane = tid & 15;
    if (rr >= n_rows) return;
    int key = row_base + rr;

    const float* src0;
    const float* src1;
    int U_split;
    if (key < N_) {                    // graph: concat(user, item) source
        src0 = user_emb; src1 = item_emb; U_split = U_;
    } else if (key < N_ + U_) {        // user SpMM
        src0 = user_emb; src1 = user_emb; U_split = 0x7FFFFFFF;
    } else {                           // item SpMM
        src0 = item_emb; src1 = item_emb; U_split = 0x7FFFFFFF;
    }

    int deg = min(d_curs[key], CAP);
    const int2* bucket = d_perm + (size_t)key * CAP;

    float4 acc = make_float4(0.f, 0.f, 0.f, 0.f);

    int j = 0;
    for (; j + 4 <= deg; j += 4) {
        int2 e0 = __ldcs(bucket + j);
        int2 e1 = __ldcs(bucket + j + 1);
        int2 e2 = __ldcs(bucket + j + 2);
        int2 e3 = __ldcs(bucket + j + 3);
        const float* p0 = (e0.x < U_split) ? src0 + (long long)e0.x * D64 : src1 + (long long)(e0.x - U_split) * D64;
        const float* p1 = (e1.x < U_split) ? src0 + (long long)e1.x * D64 : src1 + (long long)(e1.x - U_split) * D64;
        const float* p2 = (e2.x < U_split) ? src0 + (long long)e2.x * D64 : src1 + (long long)(e2.x - U_split) * D64;
        const float* p3 = (e3.x < U_split) ? src0 + (long long)e3.x * D64 : src1 + (long long)(e3.x - U_split) * D64;
        float4 x0 = reinterpret_cast<const float4*>(p0)[lane];
        float4 x1 = reinterpret_cast<const float4*>(p1)[lane];
        float4 x2 = reinterpret_cast<const float4*>(p2)[lane];
        float4 x3 = reinterpret_cast<const float4*>(p3)[lane];
        float v0 = __int_as_float(e0.y), v1 = __int_as_float(e1.y);
        float v2 = __int_as_float(e2.y), v3 = __int_as_float(e3.y);
        acc.x = fmaf(v0, x0.x, acc.x); acc.y = fmaf(v0, x0.y, acc.y); acc.z = fmaf(v0, x0.z, acc.z); acc.w = fmaf(v0, x0.w, acc.w);
        acc.x = fmaf(v1, x1.x, acc.x); acc.y = fmaf(v1, x1.y, acc.y); acc.z = fmaf(v1, x1.z, acc.z); acc.w = fmaf(v1, x1.w, acc.w);
        acc.x = fmaf(v2, x2.x, acc.x); acc.y = fmaf(v2, x2.y, acc.y); acc.z = fmaf(v2, x2.z, acc.z); acc.w = fmaf(v2, x2.w, acc.w);
        acc.x = fmaf(v3, x3.x, acc.x); acc.y = fmaf(v3, x3.y, acc.y); acc.z = fmaf(v3, x3.z, acc.z); acc.w = fmaf(v3, x3.w, acc.w);
    }
    for (; j < deg; j++) {
        int2 e = __ldcs(bucket + j);
        const float* p = (e.x < U_split) ? src0 + (long long)e.x * D64 : src1 + (long long)(e.x - U_split) * D64;
        float4 x = reinterpret_cast<const float4*>(p)[lane];
        float v = __int_as_float(e.y);
        acc.x = fmaf(v, x.x, acc.x); acc.y = fmaf(v, x.y, acc.y);
        acc.z = fmaf(v, x.z, acc.z); acc.w = fmaf(v, x.w, acc.w);
    }

    __stcs(reinterpret_cast<float4*>(out + (long long)key * D64) + lane, acc);
}

// ---------------- overflow fixup (exactness; small) ----------------
__global__ void __launch_bounds__(TPB) fixup(const float* __restrict__ user_emb,
                                             const float* __restrict__ item_emb,
                                             float* __restrict__ out,
                                             int N_, int U_) {
    int n = min(d_ovf_count, OVF_CAP);
    long long total = (long long)n * 16;
    for (long long t = blockIdx.x * (long long)TPB + threadIdx.x; t < total;
         t += (long long)gridDim.x * TPB) {
        int idx  = (int)(t >> 4);
        int lane = (int)(t & 15);
        int4 e = d_ovf[idx];
        int key = e.x, c = e.y;
        float v = __int_as_float(e.z);
        const float* src;
        if (key < N_)            src = (c < U_) ? user_emb + (long long)c * D64
                                                : item_emb + (long long)(c - U_) * D64;
        else if (key < N_ + U_)  src = user_emb + (long long)c * D64;
        else                     src = item_emb + (long long)c * D64;
        float4 x = reinterpret_cast<const float4*>(src)[lane];
        x.x *= v; x.y *= v; x.z *= v; x.w *= v;
        float4* d = reinterpret_cast<float4*>(out + (long long)key * D64) + lane;
        asm volatile("red.global.add.v4.f32 [%0], {%1,%2,%3,%4};"
                     :: "l"(d), "f"(x.x), "f"(x.y), "f"(x.z), "f"(x.w)
                     : "memory");
    }
}

extern "C" void kernel_launch(void* const* d_in, const int* in_sizes, int n_in,
                              void* d_out, int out_size) {
    const float* user_emb = (const float*)d_in[0];
    const float* item_emb = (const float*)d_in[1];
    const int*   g_rows = (const int*)d_in[2];
    const int*   g_cols = (const int*)d_in[3];
    const float* g_vals = (const float*)d_in[4];
    const int*   u_rows = (const int*)d_in[5];
    const int*   u_cols = (const int*)d_in[6];
    const float* u_vals = (const float*)d_in[7];
    const int*   i_rows = (const int*)d_in[8];
    const int*   i_cols = (const int*)d_in[9];
    const float* i_vals = (const float*)d_in[10];

    float* out = (float*)d_out;

    const int U_ = in_sizes[0] / D64;   // 100000
    const int I_ = in_sizes[1] / D64;   // 50000
    const int N_ = U_ + I_;
    const int EG = in_sizes[2];
    const int EU = in_sizes[5];
    const int EI = in_sizes[8];
    const int ROWS = N_ + U_ + I_;

    // Zero cursors + overflow counter.
    void* curs_ptr = nullptr;
    cudaGetSymbolAddress(&curs_ptr, d_curs);
    cudaMemsetAsync(curs_ptr, 0, (size_t)ROWS * sizeof(int), 0);
    void* ovf_ptr = nullptr;
    cudaGetSymbolAddress(&ovf_ptr, d_ovf_count);
    cudaMemsetAsync(ovf_ptr, 0, sizeof(int), 0);

    cudaStream_t s2;
    cudaStreamCreateWithFlags(&s2, cudaStreamNonBlocking);
    cudaEvent_t evUI, evJoin;
    cudaEventCreateWithFlags(&evUI,   cudaEventDisableTiming);
    cudaEventCreateWithFlags(&evJoin, cudaEventDisableTiming);

    // Phase 1 (s0): user+item scatter, full machine. (serial — same resource
    // as scatterG, no point overlapping)
    {
        int ET = EU + EI;
        scatter_ui<<<(ET + TPB - 1) / TPB, TPB>>>(u_rows, u_cols, u_vals,
                                                  i_rows, i_cols, i_vals,
                                                  EU, EI, N_, U_);
        cudaEventRecord(evUI, 0);
    }

    // Phase 2: heterogeneous overlap. mainUI (LTS-BW-bound) on s2 runs
    // concurrently with scatterG (wavefront-bound) and then mainG on s0.
    cudaStreamWaitEvent(s2, evUI, 0);
    {
        int n_rows = U_ + I_;
        int blocks = (n_rows * 16 + TPB - 1) / TPB;
        csr_spmm_range<<<blocks, TPB, 0, s2>>>(user_emb, item_emb, out,
                                               N_, n_rows, N_, U_);
        cudaEventRecord(evJoin, s2);
    }

    scatter_list<<<(EG + TPB - 1) / TPB, TPB>>>(g_rows, g_cols, g_vals, EG, 0);
    {
        int blocks = (N_ * 16 + TPB - 1) / TPB;
        csr_spmm_range<<<blocks, TPB>>>(user_emb, item_emb, out, 0, N_, N_, U_);
    }

    // Join + exact overflow fixup.
    cudaStreamWaitEvent(0, evJoin, 0);
    fixup<<<64, TPB>>>(user_emb, item_emb, out, N_, U_);

    cudaEventDestroy(evUI);
    cudaEventDestroy(evJoin);
    cudaStreamDestroy(s2);
}